// round 4
// baseline (speedup 1.0000x reference)
#include <cuda_runtime.h>
#include <cstdint>

// SpikeFP32Embedding: out[t, :] = weight_pulse[token_ids[t], :]
// weight_pulse: [32768, 128, 32] fp32  -> 4096 floats = 1024 float4 per row
// token_ids:    [8, 2048] int32        -> 16384 tokens
// out:          [16384, 4096] fp32
//
// Pure HBM-bound gather-copy. One CTA per token; 256 threads x 4 float4.
// Reads through L2 (token repeats get reuse), writes with .cs streaming hint
// (output is write-once, never re-read -> keep L2 capacity for the table).

static constexpr int ROW_F4   = 1024;   // 4096 floats / 4
static constexpr int THREADS  = 256;
static constexpr int F4_PER_T = ROW_F4 / THREADS;  // 4

__device__ __forceinline__ void stcs_f4(float4* addr, const float4& v) {
    asm volatile("st.global.cs.v4.f32 [%0], {%1, %2, %3, %4};"
                 :: "l"(addr), "f"(v.x), "f"(v.y), "f"(v.z), "f"(v.w)
                 : "memory");
}

__global__ void __launch_bounds__(THREADS)
spike_embed_gather(const int* __restrict__ token_ids,
                   const float4* __restrict__ table,
                   float4* __restrict__ out)
{
    const int tok = blockIdx.x;
    const int row = __ldg(&token_ids[tok]);

    const float4* __restrict__ src = table + (size_t)row * ROW_F4;
    float4* __restrict__       dst = out   + (size_t)tok * ROW_F4;

    const int tid = threadIdx.x;
    float4 v[F4_PER_T];
#pragma unroll
    for (int i = 0; i < F4_PER_T; ++i)
        v[i] = __ldg(&src[tid + i * THREADS]);
#pragma unroll
    for (int i = 0; i < F4_PER_T; ++i)
        stcs_f4(&dst[tid + i * THREADS], v[i]);
}

extern "C" void kernel_launch(void* const* d_in, const int* in_sizes, int n_in,
                              void* d_out, int out_size)
{
    // Resolve input order by element count (robust to metadata ordering):
    //   token_ids:    8*2048            = 16384
    //   weight_pulse: 32768*128*32      = 134217728
    const int* token_ids = nullptr;
    const float4* table  = nullptr;
    for (int i = 0; i < n_in; ++i) {
        if (in_sizes[i] == 16384)          token_ids = (const int*)d_in[i];
        else if (in_sizes[i] == 134217728) table     = (const float4*)d_in[i];
    }

    const int n_tokens = 16384;
    spike_embed_gather<<<n_tokens, THREADS>>>(token_ids, table, (float4*)d_out);
}